// round 8
// baseline (speedup 1.0000x reference)
#include <cuda_runtime.h>
#include <cuda_fp16.h>
#include <cstdint>

// Problem dims fixed by dataset: M = 8*4096 = 32768, K = 1024, N = 1024.
#define M_TOTAL 32768
#define N_DIM   1024
#define K_DIM   1024

#define BM 256
#define BN 128
#define BK 64
#define NSTAGES 3
#define NKT (K_DIM / BK)            // 16 k-tiles

// 128B rows (64 halfs), SW128 XOR swizzle, no padding.
#define A_TILE_BYTES (BM * 128)     // 32768
#define B_TILE_BYTES (BN * 128)     // 16384
#define STAGE_BYTES (A_TILE_BYTES + B_TILE_BYTES)      // 49152
#define SMEM_BYTES (NSTAGES * STAGE_BYTES)             // 147456

// Scratch (no allocations allowed)
__device__ float  g_partial[256];
__device__ __half g_Bh[(size_t)N_DIM * K_DIM];      // ternary weight fp16, [n][k]
__device__ __half g_Ah[(size_t)M_TOTAL * K_DIM];    // input fp16, 64 MB

// ---------------------------------------------------------------------------
__device__ __forceinline__ uint32_t smem_u32(const void* p) {
    uint32_t a;
    asm("{ .reg .u64 t; cvta.to.shared.u64 t, %1; cvt.u32.u64 %0, t; }" : "=r"(a) : "l"(p));
    return a;
}
__device__ __forceinline__ void cp_async_16(uint32_t dst, const void* src) {
    asm volatile("cp.async.cg.shared.global [%0], [%1], 16;" :: "r"(dst), "l"(src) : "memory");
}
__device__ __forceinline__ void cp_commit() {
    asm volatile("cp.async.commit_group;" ::: "memory");
}
template <int N>
__device__ __forceinline__ void cp_wait_group() {
    asm volatile("cp.async.wait_group %0;" :: "n"(N) : "memory");
}
__device__ __forceinline__ void ldmatrix_x4(uint32_t& r0, uint32_t& r1, uint32_t& r2,
                                            uint32_t& r3, uint32_t addr) {
    asm volatile("ldmatrix.sync.aligned.m8n8.x4.shared.b16 {%0,%1,%2,%3}, [%4];"
                 : "=r"(r0), "=r"(r1), "=r"(r2), "=r"(r3) : "r"(addr));
}
__device__ __forceinline__ void mma16816(float* c, const uint32_t* a, const uint32_t* b) {
    asm volatile(
        "mma.sync.aligned.m16n8k16.row.col.f32.f16.f16.f32 "
        "{%0,%1,%2,%3}, {%4,%5,%6,%7}, {%8,%9}, {%0,%1,%2,%3};"
        : "+f"(c[0]), "+f"(c[1]), "+f"(c[2]), "+f"(c[3])
        : "r"(a[0]), "r"(a[1]), "r"(a[2]), "r"(a[3]), "r"(b[0]), "r"(b[1]));
}

// ---------------------------------------------------------------------------
// 1) deterministic sum of |W|
// ---------------------------------------------------------------------------
__global__ void reduce_abs_kernel(const float* __restrict__ w) {
    __shared__ float sdata[256];
    int tid = threadIdx.x;
    int base = blockIdx.x * 4096 + tid;
    float s = 0.f;
#pragma unroll
    for (int i = 0; i < 16; i++) s += fabsf(w[base + i * 256]);
    sdata[tid] = s;
    __syncthreads();
    for (int off = 128; off > 0; off >>= 1) {
        if (tid < off) sdata[tid] += sdata[tid + off];
        __syncthreads();
    }
    if (tid == 0) g_partial[blockIdx.x] = sdata[0];
}

// ---------------------------------------------------------------------------
// 2) delta + ternary quantize into fp16 B[n][k]
// ---------------------------------------------------------------------------
__global__ void quantize_kernel(const float* __restrict__ w) {
    __shared__ float s_delta;
    if (threadIdx.x == 0) {
        double t = 0.0;
        for (int i = 0; i < 256; i++) t += (double)g_partial[i];
        s_delta = (float)(0.7 * t / 1048576.0);
    }
    __syncthreads();
    float delta = s_delta;
    int n = blockIdx.x, k = threadIdx.x;
    float v = w[n * K_DIM + k];
    float q = (v > delta) ? 1.f : ((v < -delta) ? -1.f : 0.f);
    g_Bh[(size_t)n * K_DIM + k] = __float2half_rn(q);
}

// ---------------------------------------------------------------------------
// 3) convert x fp32 -> fp16 (8 elems / thread, 16B stores)
// ---------------------------------------------------------------------------
__global__ void convert_kernel(const float* __restrict__ x) {
    size_t i = (size_t)blockIdx.x * blockDim.x + threadIdx.x;
    const float4* xv = reinterpret_cast<const float4*>(x) + i * 2;
    float4 a = xv[0], b = xv[1];
    __half2 h0 = __floats2half2_rn(a.x, a.y);
    __half2 h1 = __floats2half2_rn(a.z, a.w);
    __half2 h2 = __floats2half2_rn(b.x, b.y);
    __half2 h3 = __floats2half2_rn(b.z, b.w);
    uint4 o;
    o.x = *reinterpret_cast<uint32_t*>(&h0);
    o.y = *reinterpret_cast<uint32_t*>(&h1);
    o.z = *reinterpret_cast<uint32_t*>(&h2);
    o.w = *reinterpret_cast<uint32_t*>(&h3);
    reinterpret_cast<uint4*>(g_Ah)[i] = o;
}

// ---------------------------------------------------------------------------
// 4) Pipelined HMMA GEMM: C = alpha * (Ah @ Bh^T) + bias
//    CTA 256x128x64, 3-stage cp.async (SW128 swizzled 128B rows),
//    8 warps (4M x 2N), warp tile 64x64. 1 CTA/SM.
// ---------------------------------------------------------------------------
__global__ void __launch_bounds__(256, 1) ternary_gemm_hmma(
    const float* __restrict__ alpha_p,
    const float* __restrict__ bias,
    float* __restrict__ C)
{
    extern __shared__ __align__(1024) unsigned char smem[];
    const uint32_t sbase = smem_u32(smem);

    const int tid   = threadIdx.x;
    const int warp  = tid >> 5;
    const int lane  = tid & 31;
    const int warpM = warp & 3;    // 0..3
    const int warpN = warp >> 2;   // 0..1

    const int blockN = blockIdx.x * BN;
    const int blockM = blockIdx.y * BM;

    // ---- producer: thread -> A rows {pr0 + i*32, i<8}, B rows {pr0 + i*32, i<4} ----
    const int pr0 = tid >> 3;          // 0..31
    const int pc  = tid & 7;           // 16B column within 128B row
    const __half* Asrc = g_Ah + (size_t)(blockM + pr0) * K_DIM + pc * 8;
    const __half* Bsrc = g_Bh + (size_t)(blockN + pr0) * K_DIM + pc * 8;
    const uint32_t pcol = (uint32_t)(pc ^ (pr0 & 7)) << 4;   // swizzled 16B col (row&7 const mod 32)

    auto issue_stage = [&](int t, int buf) {
        const uint32_t sa = sbase + buf * STAGE_BYTES;
        const uint32_t sb = sa + A_TILE_BYTES;
        const size_t ko = (size_t)t * BK;
#pragma unroll
        for (int i = 0; i < 8; i++)
            cp_async_16(sa + (uint32_t)(pr0 + i * 32) * 128 + pcol,
                        Asrc + ko + (size_t)i * 32 * K_DIM);
#pragma unroll
        for (int i = 0; i < 4; i++)
            cp_async_16(sb + (uint32_t)(pr0 + i * 32) * 128 + pcol,
                        Bsrc + ko + (size_t)i * 32 * K_DIM);
        cp_commit();
    };

    // ---- consumer addressing ----
    const uint32_t axor  = (uint32_t)(lane & 7);
    const uint32_t aRowB = (uint32_t)(warpM * 64 + (lane & 15)) * 128;   // + mi*2048
    const uint32_t aCbit = (uint32_t)((lane >> 4) & 1);
    const uint32_t bRowB = (uint32_t)(warpN * 64 + (lane & 7) + ((lane >> 4) << 3)) * 128; // + nb*2048
    const uint32_t bCbit = (uint32_t)((lane >> 3) & 1);

    float c[4][8][4];
#pragma unroll
    for (int i = 0; i < 4; i++)
#pragma unroll
        for (int j = 0; j < 8; j++)
#pragma unroll
            for (int e = 0; e < 4; e++) c[i][j][e] = 0.f;

    issue_stage(0, 0);
    issue_stage(1, 1);

    int sc = 0;
    for (int t = 0; t < NKT; t++) {
        cp_wait_group<1>();
        __syncthreads();
        if (t + 2 < NKT) {
            int pb = sc + 2; if (pb >= NSTAGES) pb -= NSTAGES;
            issue_stage(t + 2, pb);
        }

        const uint32_t sa = sbase + sc * STAGE_BYTES;
        const uint32_t sb = sa + A_TILE_BYTES;

#pragma unroll
        for (int ks = 0; ks < 4; ks++) {
            const uint32_t ac = ((uint32_t)(ks * 2) + aCbit) ^ axor;
            const uint32_t bc = ((uint32_t)(ks * 2) + bCbit) ^ axor;
            uint32_t af[4][4], bq[4][4];
#pragma unroll
            for (int mi = 0; mi < 4; mi++)
                ldmatrix_x4(af[mi][0], af[mi][1], af[mi][2], af[mi][3],
                            sa + aRowB + mi * 2048 + (ac << 4));
#pragma unroll
            for (int nb = 0; nb < 4; nb++)
                ldmatrix_x4(bq[nb][0], bq[nb][1], bq[nb][2], bq[nb][3],
                            sb + bRowB + nb * 2048 + (bc << 4));
#pragma unroll
            for (int mi = 0; mi < 4; mi++) {
#pragma unroll
                for (int nj = 0; nj < 8; nj++) {
                    uint32_t bfr[2] = { bq[nj >> 1][(nj & 1) * 2], bq[nj >> 1][(nj & 1) * 2 + 1] };
                    mma16816(c[mi][nj], af[mi], bfr);
                }
            }
        }
        __syncthreads();   // phase-lock; protects buffer reuse
        if (++sc == NSTAGES) sc = 0;
    }

    // ---- epilogue: alpha * acc + bias, direct stores ----
    const float alpha = __ldg(alpha_p);
    const int gColBase = blockN + warpN * 64 + (lane & 3) * 2;
    const int gRowBase = blockM + warpM * 64 + (lane >> 2);

#pragma unroll
    for (int mi = 0; mi < 4; mi++) {
        float* r0 = C + (size_t)(gRowBase + mi * 16) * N_DIM;
        float* r1 = r0 + (size_t)8 * N_DIM;
#pragma unroll
        for (int nj = 0; nj < 8; nj++) {
            float2 bv = *reinterpret_cast<const float2*>(bias + gColBase + nj * 8);
            float2 o0, o1;
            o0.x = fmaf(alpha, c[mi][nj][0], bv.x);
            o0.y = fmaf(alpha, c[mi][nj][1], bv.y);
            o1.x = fmaf(alpha, c[mi][nj][2], bv.x);
            o1.y = fmaf(alpha, c[mi][nj][3], bv.y);
            *reinterpret_cast<float2*>(r0 + gColBase + nj * 8) = o0;
            *reinterpret_cast<float2*>(r1 + gColBase + nj * 8) = o1;
        }
    }
}

// ---------------------------------------------------------------------------
// Inputs: 0=input [8,4096,1024] f32, 1=weight [1024,1024] f32, 2=alpha [1], 3=bias [1024]
// ---------------------------------------------------------------------------
extern "C" void kernel_launch(void* const* d_in, const int* in_sizes, int n_in,
                              void* d_out, int out_size) {
    const float* x     = (const float*)d_in[0];
    const float* w     = (const float*)d_in[1];
    const float* alpha = (const float*)d_in[2];
    const float* bias  = (const float*)d_in[3];
    float* out = (float*)d_out;

    cudaFuncSetAttribute(ternary_gemm_hmma, cudaFuncAttributeMaxDynamicSharedMemorySize, SMEM_BYTES);

    reduce_abs_kernel<<<256, 256>>>(w);
    quantize_kernel<<<1024, 1024>>>(w);
    convert_kernel<<<16384, 256>>>(x);

    dim3 grid(N_DIM / BN, M_TOTAL / BM);   // (8, 128) — x fastest => B reuse through L2
    ternary_gemm_hmma<<<grid, 256, SMEM_BYTES>>>(alpha, bias, out);
}

// round 10
// speedup vs baseline: 1.1100x; 1.1100x over previous
#include <cuda_runtime.h>
#include <cuda_fp16.h>
#include <cstdint>

// Problem dims fixed by dataset: M = 8*4096 = 32768, K = 1024, N = 1024.
#define M_TOTAL 32768
#define N_DIM   1024
#define K_DIM   1024

#define BM 128
#define BN 128
#define BK 64
#define NSTAGES 3
#define NKT (K_DIM / BK)            // 16 k-tiles

// 128B rows (64 halfs), SW128 XOR swizzle, no padding.
#define A_TILE_BYTES (BM * 128)     // 16384
#define B_TILE_BYTES (BN * 128)     // 16384
#define STAGE_BYTES (A_TILE_BYTES + B_TILE_BYTES)      // 32768
#define SMEM_BYTES (NSTAGES * STAGE_BYTES)             // 98304 -> 2 CTAs/SM

// Scratch (no allocations allowed)
__device__ float  g_partial[256];
__device__ __half g_Bh[(size_t)N_DIM * K_DIM];      // ternary weight fp16, [n][k]
__device__ __half g_Ah[(size_t)M_TOTAL * K_DIM];    // input fp16, 64 MB

// ---------------------------------------------------------------------------
__device__ __forceinline__ uint32_t smem_u32(const void* p) {
    uint32_t a;
    asm("{ .reg .u64 t; cvta.to.shared.u64 t, %1; cvt.u32.u64 %0, t; }" : "=r"(a) : "l"(p));
    return a;
}
__device__ __forceinline__ void cp_async_16(uint32_t dst, const void* src) {
    asm volatile("cp.async.cg.shared.global [%0], [%1], 16;" :: "r"(dst), "l"(src) : "memory");
}
__device__ __forceinline__ void cp_commit() {
    asm volatile("cp.async.commit_group;" ::: "memory");
}
template <int N>
__device__ __forceinline__ void cp_wait_group() {
    asm volatile("cp.async.wait_group %0;" :: "n"(N) : "memory");
}
__device__ __forceinline__ void ldmatrix_x4(uint32_t& r0, uint32_t& r1, uint32_t& r2,
                                            uint32_t& r3, uint32_t addr) {
    asm volatile("ldmatrix.sync.aligned.m8n8.x4.shared.b16 {%0,%1,%2,%3}, [%4];"
                 : "=r"(r0), "=r"(r1), "=r"(r2), "=r"(r3) : "r"(addr));
}
__device__ __forceinline__ void mma16816(float* c, const uint32_t* a, const uint32_t* b) {
    asm volatile(
        "mma.sync.aligned.m16n8k16.row.col.f32.f16.f16.f32 "
        "{%0,%1,%2,%3}, {%4,%5,%6,%7}, {%8,%9}, {%0,%1,%2,%3};"
        : "+f"(c[0]), "+f"(c[1]), "+f"(c[2]), "+f"(c[3])
        : "r"(a[0]), "r"(a[1]), "r"(a[2]), "r"(a[3]), "r"(b[0]), "r"(b[1]));
}

// ---------------------------------------------------------------------------
// 1) deterministic sum of |W|
// ---------------------------------------------------------------------------
__global__ void reduce_abs_kernel(const float* __restrict__ w) {
    __shared__ float sdata[256];
    int tid = threadIdx.x;
    int base = blockIdx.x * 4096 + tid;
    float s = 0.f;
#pragma unroll
    for (int i = 0; i < 16; i++) s += fabsf(w[base + i * 256]);
    sdata[tid] = s;
    __syncthreads();
    for (int off = 128; off > 0; off >>= 1) {
        if (tid < off) sdata[tid] += sdata[tid + off];
        __syncthreads();
    }
    if (tid == 0) g_partial[blockIdx.x] = sdata[0];
}

// ---------------------------------------------------------------------------
// 2) delta + ternary quantize into fp16 B[n][k]
// ---------------------------------------------------------------------------
__global__ void quantize_kernel(const float* __restrict__ w) {
    __shared__ float s_delta;
    if (threadIdx.x == 0) {
        double t = 0.0;
        for (int i = 0; i < 256; i++) t += (double)g_partial[i];
        s_delta = (float)(0.7 * t / 1048576.0);
    }
    __syncthreads();
    float delta = s_delta;
    int n = blockIdx.x, k = threadIdx.x;
    float v = w[n * K_DIM + k];
    float q = (v > delta) ? 1.f : ((v < -delta) ? -1.f : 0.f);
    g_Bh[(size_t)n * K_DIM + k] = __float2half_rn(q);
}

// ---------------------------------------------------------------------------
// 3) convert x fp32 -> fp16 (8 elems / thread, 16B stores)
// ---------------------------------------------------------------------------
__global__ void convert_kernel(const float* __restrict__ x) {
    size_t i = (size_t)blockIdx.x * blockDim.x + threadIdx.x;
    const float4* xv = reinterpret_cast<const float4*>(x) + i * 2;
    float4 a = xv[0], b = xv[1];
    __half2 h0 = __floats2half2_rn(a.x, a.y);
    __half2 h1 = __floats2half2_rn(a.z, a.w);
    __half2 h2 = __floats2half2_rn(b.x, b.y);
    __half2 h3 = __floats2half2_rn(b.z, b.w);
    uint4 o;
    o.x = *reinterpret_cast<uint32_t*>(&h0);
    o.y = *reinterpret_cast<uint32_t*>(&h1);
    o.z = *reinterpret_cast<uint32_t*>(&h2);
    o.w = *reinterpret_cast<uint32_t*>(&h3);
    reinterpret_cast<uint4*>(g_Ah)[i] = o;
}

// ---------------------------------------------------------------------------
// 4) Pipelined HMMA GEMM: C = alpha * (Ah @ Bh^T) + bias
//    CTA 128x128x64, 4 warps (2M x 2N), warp tile 64x64, 128 threads,
//    3-stage cp.async, SW128 swizzle, 2 independent CTAs/SM.
// ---------------------------------------------------------------------------
__global__ void __launch_bounds__(128, 2) ternary_gemm_hmma(
    const float* __restrict__ alpha_p,
    const float* __restrict__ bias,
    float* __restrict__ C)
{
    extern __shared__ __align__(1024) unsigned char smem[];
    const uint32_t sbase = smem_u32(smem);

    const int tid   = threadIdx.x;
    const int warp  = tid >> 5;
    const int lane  = tid & 31;
    const int warpM = warp & 1;    // 0..1
    const int warpN = warp >> 1;   // 0..1

    const int blockN = blockIdx.x * BN;
    const int blockM = blockIdx.y * BM;

    // ---- producer: 128 threads, 16 x 16B chunks each per stage (8 A + 8 B) ----
    const int pr0 = tid >> 3;          // 0..15
    const int pc  = tid & 7;           // 16B column within 128B row
    const __half* Asrc = g_Ah + (size_t)(blockM + pr0) * K_DIM + pc * 8;
    const __half* Bsrc = g_Bh + (size_t)(blockN + pr0) * K_DIM + pc * 8;
    const uint32_t pcol = (uint32_t)(pc ^ (pr0 & 7)) << 4;   // (pr0+16i)&7 == pr0&7

    auto issue_stage = [&](int t, int buf) {
        const uint32_t sa = sbase + buf * STAGE_BYTES;
        const uint32_t sb = sa + A_TILE_BYTES;
        const size_t ko = (size_t)t * BK;
#pragma unroll
        for (int i = 0; i < 8; i++)
            cp_async_16(sa + (uint32_t)(pr0 + i * 16) * 128 + pcol,
                        Asrc + ko + (size_t)i * 16 * K_DIM);
#pragma unroll
        for (int i = 0; i < 8; i++)
            cp_async_16(sb + (uint32_t)(pr0 + i * 16) * 128 + pcol,
                        Bsrc + ko + (size_t)i * 16 * K_DIM);
        cp_commit();
    };

    // ---- consumer addressing ----
    const uint32_t axor  = (uint32_t)(lane & 7);
    const uint32_t aRowB = (uint32_t)(warpM * 64 + (lane & 15)) * 128;   // + mi*2048
    const uint32_t aCbit = (uint32_t)((lane >> 4) & 1);
    const uint32_t bRowB = (uint32_t)(warpN * 64 + (lane & 7) + ((lane >> 4) << 3)) * 128; // + nb*2048
    const uint32_t bCbit = (uint32_t)((lane >> 3) & 1);

    float c[4][8][4];
#pragma unroll
    for (int i = 0; i < 4; i++)
#pragma unroll
        for (int j = 0; j < 8; j++)
#pragma unroll
            for (int e = 0; e < 4; e++) c[i][j][e] = 0.f;

    issue_stage(0, 0);
    issue_stage(1, 1);

    int sc = 0;
    for (int t = 0; t < NKT; t++) {
        cp_wait_group<1>();
        __syncthreads();
        if (t + 2 < NKT) {
            int pb = sc + 2; if (pb >= NSTAGES) pb -= NSTAGES;
            issue_stage(t + 2, pb);
        }

        const uint32_t sa = sbase + sc * STAGE_BYTES;
        const uint32_t sb = sa + A_TILE_BYTES;

#pragma unroll
        for (int ks = 0; ks < 4; ks++) {
            const uint32_t ac = ((uint32_t)(ks * 2) + aCbit) ^ axor;
            const uint32_t bc = ((uint32_t)(ks * 2) + bCbit) ^ axor;
            uint32_t af[4][4], bq[4][4];
#pragma unroll
            for (int mi = 0; mi < 4; mi++)
                ldmatrix_x4(af[mi][0], af[mi][1], af[mi][2], af[mi][3],
                            sa + aRowB + mi * 2048 + (ac << 4));
#pragma unroll
            for (int nb = 0; nb < 4; nb++)
                ldmatrix_x4(bq[nb][0], bq[nb][1], bq[nb][2], bq[nb][3],
                            sb + bRowB + nb * 2048 + (bc << 4));
#pragma unroll
            for (int mi = 0; mi < 4; mi++) {
#pragma unroll
                for (int nj = 0; nj < 8; nj++) {
                    uint32_t bfr[2] = { bq[nj >> 1][(nj & 1) * 2], bq[nj >> 1][(nj & 1) * 2 + 1] };
                    mma16816(c[mi][nj], af[mi], bfr);
                }
            }
        }
        __syncthreads();   // phase-lock; protects buffer reuse
        if (++sc == NSTAGES) sc = 0;
    }

    // ---- epilogue: alpha * acc + bias, direct stores ----
    const float alpha = __ldg(alpha_p);
    const int gColBase = blockN + warpN * 64 + (lane & 3) * 2;
    const int gRowBase = blockM + warpM * 64 + (lane >> 2);

#pragma unroll
    for (int mi = 0; mi < 4; mi++) {
        float* r0 = C + (size_t)(gRowBase + mi * 16) * N_DIM;
        float* r1 = r0 + (size_t)8 * N_DIM;
#pragma unroll
        for (int nj = 0; nj < 8; nj++) {
            float2 bv = *reinterpret_cast<const float2*>(bias + gColBase + nj * 8);
            float2 o0, o1;
            o0.x = fmaf(alpha, c[mi][nj][0], bv.x);
            o0.y = fmaf(alpha, c[mi][nj][1], bv.y);
            o1.x = fmaf(alpha, c[mi][nj][2], bv.x);
            o1.y = fmaf(alpha, c[mi][nj][3], bv.y);
            *reinterpret_cast<float2*>(r0 + gColBase + nj * 8) = o0;
            *reinterpret_cast<float2*>(r1 + gColBase + nj * 8) = o1;
        }
    }
}

// ---------------------------------------------------------------------------
// Inputs: 0=input [8,4096,1024] f32, 1=weight [1024,1024] f32, 2=alpha [1], 3=bias [1024]
// ---------------------------------------------------------------------------
extern "C" void kernel_launch(void* const* d_in, const int* in_sizes, int n_in,
                              void* d_out, int out_size) {
    const float* x     = (const float*)d_in[0];
    const float* w     = (const float*)d_in[1];
    const float* alpha = (const float*)d_in[2];
    const float* bias  = (const float*)d_in[3];
    float* out = (float*)d_out;

    cudaFuncSetAttribute(ternary_gemm_hmma, cudaFuncAttributeMaxDynamicSharedMemorySize, SMEM_BYTES);

    reduce_abs_kernel<<<256, 256>>>(w);
    quantize_kernel<<<1024, 1024>>>(w);
    convert_kernel<<<16384, 256>>>(x);

    dim3 grid(N_DIM / BN, M_TOTAL / BM);   // (8, 256) — x fastest => B reuse through L2
    ternary_gemm_hmma<<<grid, 128, SMEM_BYTES>>>(alpha, bias, out);
}